// round 11
// baseline (speedup 1.0000x reference)
#include <cuda_runtime.h>
#include <stdint.h>

#define N_NODES_MAX 100000
#define E_MAX       1200000
#define EP_MAX      (E_MAX + 4 * N_NODES_MAX)   // CSR padded to multiple-of-4 rows
#define NFEAT 64
#define NHID  256
#define NCLASS 40
#define ORDER 8

// ---------------- scratch (device globals; no allocation) ----------------
__device__ __align__(256) float g_h0[N_NODES_MAX * NFEAT];
__device__ __align__(256) float g_h1[N_NODES_MAX * NFEAT];
__device__ __align__(256) float g_y [N_NODES_MAX * NFEAT];
// combined zero-initialized workspace: [0,N)=cnt, [N,2N)=fill, [2N,2N+256)=scan flags
__device__ int   g_ws[2 * N_NODES_MAX + 256];
__device__ float g_dinv[N_NODES_MAX];
__device__ int   g_rowptr[N_NODES_MAX + 1];
__device__ __align__(16) int   g_col[EP_MAX];  // PRE-SCALED byte offsets (col*256); pads = 0
__device__ __align__(16) float g_w  [EP_MAX];  // pad slots = 0.0f (exact no-op in fmaf)

#define CNT(i)  g_ws[i]
#define FILL(i) g_ws[N_NODES_MAX + (i)]
#define FLAG(b) g_ws[2 * N_NODES_MAX + (b)]

// ---------------- edge-index dtype self-detection ----------------
// Reference asks int64 but JAX without x64 silently yields int32. Node ids
// < 1e5, so int32 data reinterpreted as int64 gives values >= 2^32 unless a
// paired high id is exactly 0 (1e-5 per sample; 8 samples -> (1e-5)^8).
__device__ __forceinline__ int detect_is64(const void* ei) {
    const unsigned long long* p = (const unsigned long long*)ei;
    int is64 = 1;
    #pragma unroll
    for (int i = 0; i < 8; i++)
        if (p[i] >= (unsigned long long)N_NODES_MAX) is64 = 0;
    return is64;
}

__device__ __forceinline__ int edge_at(const void* ei, int is64, int idx) {
    if (is64) return (int)((const long long*)ei)[idx];
    return ((const int*)ei)[idx];
}

// Vectorized: load 4 consecutive edge ids starting at idx (idx 4-aligned).
__device__ __forceinline__ void edge_at4(const void* ei, int is64, int idx,
                                         int out[4]) {
    if (is64) {
        const longlong2* p = (const longlong2*)((const long long*)ei + idx);
        longlong2 a = __ldg(&p[0]);
        longlong2 b = __ldg(&p[1]);
        out[0] = (int)a.x; out[1] = (int)a.y;
        out[2] = (int)b.x; out[3] = (int)b.y;
    } else {
        int4 a = __ldg((const int4*)((const int*)ei + idx));
        out[0] = a.x; out[1] = a.y; out[2] = a.z; out[3] = a.w;
    }
}

// ---------------- preprocessing ----------------
// 4 edges per thread, vectorized loads -> 4 atomics in flight per thread.
__global__ void k_hist(const void* __restrict__ ei, int E) {
    int e0 = (blockIdx.x * blockDim.x + threadIdx.x) * 4;
    if (e0 >= E) return;
    int is64 = detect_is64(ei);
    if (e0 + 4 <= E) {
        int r[4];
        edge_at4(ei, is64, e0, r);
        #pragma unroll
        for (int t = 0; t < 4; t++) atomicAdd(&CNT(r[t]), 1);
    } else {
        for (int e = e0; e < E; e++)
            atomicAdd(&CNT(edge_at(ei, is64, e)), 1);
    }
}

// Fused: dinv + exclusive scan of PADDED degree counts -> rowptr.
// Padded degree = (deg+3)&~3 so the SPMM inner loop is branch-free 4-wide
// AND every rowptr is a multiple of 4 (16B-aligned col/w groups).
// StreamScan: 98 resident blocks (< 148 SMs, deadlock-free), serial FLAG
// chain; each waiter polls a DISTINCT address -> no atomic contention.
__global__ __launch_bounds__(1024) void k_scan(int n, int ntiles) {
    __shared__ int s[1024];
    __shared__ int s_prefix;
    int tid = threadIdx.x;
    int b   = blockIdx.x;
    int i   = b * 1024 + tid;
    int c   = (i < n) ? CNT(i) : 0;
    int cp  = (c + 3) & ~3;                          // padded degree
    if (i < n) g_dinv[i] = rsqrtf((float)(c + 1));   // +1 self-loop (actual deg)
    s[tid] = cp;
    __syncthreads();
    #pragma unroll
    for (int off = 1; off < 1024; off <<= 1) {
        int t = (tid >= off) ? s[tid - off] : 0;
        __syncthreads();
        s[tid] += t;
        __syncthreads();
    }
    if (tid == 1023) {
        int prefix = 0;
        if (b > 0) {
            int v;
            do { v = atomicAdd(&FLAG(b - 1), 0); } while (v == 0);
            prefix = v - 1;
        }
        atomicExch(&FLAG(b), prefix + s[1023] + 1);
        s_prefix = prefix;
        if (b == ntiles - 1) g_rowptr[n] = prefix + s[1023];  // total padded
    }
    __syncthreads();
    if (i < n) g_rowptr[i] = s_prefix + s[tid] - cp;  // exclusive
}

// Fused: CSR scatter (blocks [0,Eb)) + h0/y init (blocks [Eb, Eb+Nb)).
// Scatter: 4 edges per thread, vectorized row/col loads.
// Stores col as BYTE offset (c * NFEAT * 4) so SPMM address math is one IADD.
__global__ void k_scatter_init(const void* __restrict__ ei, int E,
                               const float4* __restrict__ x, int n4, int Eb) {
    if ((int)blockIdx.x < Eb) {
        int e0 = (blockIdx.x * blockDim.x + threadIdx.x) * 4;
        if (e0 >= E) return;
        int is64 = detect_is64(ei);
        if (e0 + 4 <= E) {
            int r[4], c[4];
            edge_at4(ei, is64, e0, r);
            edge_at4(ei, is64, E + e0, c);
            #pragma unroll
            for (int t = 0; t < 4; t++) {
                int pos = g_rowptr[r[t]] + atomicAdd(&FILL(r[t]), 1);
                g_col[pos] = c[t] * (NFEAT * 4);
                g_w[pos] = g_dinv[r[t]] * g_dinv[c[t]];
            }
        } else {
            for (int e = e0; e < E; e++) {
                int r = edge_at(ei, is64, e);
                int c = edge_at(ei, is64, E + e);
                int pos = g_rowptr[r] + atomicAdd(&FILL(r), 1);
                g_col[pos] = c * (NFEAT * 4);
                g_w[pos] = g_dinv[r] * g_dinv[c];
            }
        }
    } else {
        int i = ((int)blockIdx.x - Eb) * blockDim.x + threadIdx.x;
        if (i < n4) {
            float4 v = x[i];
            v.x *= 0.5f; v.y *= 0.5f; v.z *= 0.5f; v.w *= 0.5f;
            ((float4*)g_h0)[i] = v;
            ((float4*)g_y)[i]  = v;
        }
    }
}

// ---------------- SPMM: feature-half warps, branch-free 4-wide gathers -----
// Targets R5's measured profile (alu=29.5%, occ=51%, L2=26%).
// Warp gw: row = gw>>1, features [32*(gw&1), +32), one float per lane ->
// each gather is exactly one 128B line. Rows padded to 4k edges with
// (offset=0, w=0) filler: no predicates, no tails. rowptr multiples of 4 ->
// ONE int4 + ONE float4 uniform load per 4 edges. Streaming hints keep the
// h-source L2-resident.
__global__ __launch_bounds__(256) void k_spmm(const float* __restrict__ hsrc,
                                              float* __restrict__ hdst, int n2) {
    int gw = (blockIdx.x * blockDim.x + threadIdx.x) >> 5;
    if (gw >= n2) return;
    int lane = threadIdx.x & 31;
    int row  = gw >> 1;
    int fb   = ((gw & 1) << 5) + lane;      // feature index 0..63
    int foff = fb * 4;                      // byte offset within a row
    const char* __restrict__ hb = (const char*)hsrc;
    float dv = g_dinv[row];
    float hv = __ldg(&hsrc[row * NFEAT + fb]);
    float a0 = dv * dv * hv;                // self-loop term
    float a1 = 0.f, a2 = 0.f, a3 = 0.f;
    int beg = g_rowptr[row], end = g_rowptr[row + 1];  // both multiples of 4
    for (int j = beg; j < end; j += 4) {
        int4   oo  = __ldg((const int4*)&g_col[j]);    // 16B-aligned
        float4 wwv = __ldg((const float4*)&g_w[j]);    // 16B-aligned
        float v0 = *(const float*)(hb + oo.x + foff);
        float v1 = *(const float*)(hb + oo.y + foff);
        float v2 = *(const float*)(hb + oo.z + foff);
        float v3 = *(const float*)(hb + oo.w + foff);
        a0 = fmaf(wwv.x, v0, a0);
        a1 = fmaf(wwv.y, v1, a1);
        a2 = fmaf(wwv.z, v2, a2);
        a3 = fmaf(wwv.w, v3, a3);
    }
    float a = (a0 + a1) + (a2 + a3);
    int idx = row * NFEAT + fb;
    __stcs(&hdst[idx], a);                        // streaming: don't pollute L2
    float yy = __ldcs(&g_y[idx]);
    __stcs(&g_y[idx], yy + a);
}

// ---------------- fused MLP: relu(y/9 @ W1 + b1) @ W2 + b2 ----------------
// Targets the ~290us MLP residual inferred from R5's ledger. Weights are NOT
// staged in smem: W1 (64KB) + W2 (40KB) fit in L1 (228KB - smem) and are
// identical across blocks -> L1-resident broadcast LDGs after first touch.
// smem 168KB -> ~61.6KB => 3 blocks/SM = 24 warps/SM (was 8).
#define HID_STRIDE 257  // pad to dodge bank conflicts in GEMM2 reads
#define SMEM_FLOATS (32*64 + 32*HID_STRIDE + 4*32*40)

__global__ __launch_bounds__(256) void k_mlp(const float* __restrict__ y,
                                             const float* __restrict__ W1,
                                             const float* __restrict__ b1,
                                             const float* __restrict__ W2,
                                             const float* __restrict__ b2,
                                             float* __restrict__ out, int n) {
    extern __shared__ float sm[];
    float* ys  = sm;                    // [32][64]
    float* hid = ys + 32 * 64;          // [32][HID_STRIDE]
    float* red = hid + 32 * HID_STRIDE; // [4][32][40] split-k partials

    int tid = threadIdx.x;
    int row0 = blockIdx.x * 32;
    const float inv9 = 1.0f / 9.0f;

    for (int i = tid; i < 32 * 64; i += 256) {
        int r = i >> 6, g = row0 + r;
        ys[i] = (g < n) ? y[g * 64 + (i & 63)] * inv9 : 0.f;
    }
    __syncthreads();

    // GEMM1: warp w handles rows 4w..4w+3, lane handles cols lane*8..+7.
    // W1 read directly from global (L1-resident, 32B-aligned float4 pairs).
    int lane = tid & 31, warp = tid >> 5;
    int r0 = warp * 4;
    int c0 = lane * 8;
    float acc[4][8];
    #pragma unroll
    for (int r = 0; r < 4; r++)
        #pragma unroll
        for (int c = 0; c < 8; c++) acc[r][c] = 0.f;

    #pragma unroll 4
    for (int k = 0; k < 64; k++) {
        float4 w0 = __ldg((const float4*)&W1[k * 256 + c0]);
        float4 w1 = __ldg((const float4*)&W1[k * 256 + c0 + 4]);
        #pragma unroll
        for (int r = 0; r < 4; r++) {
            float yv = ys[(r0 + r) * 64 + k];
            acc[r][0] = fmaf(yv, w0.x, acc[r][0]);
            acc[r][1] = fmaf(yv, w0.y, acc[r][1]);
            acc[r][2] = fmaf(yv, w0.z, acc[r][2]);
            acc[r][3] = fmaf(yv, w0.w, acc[r][3]);
            acc[r][4] = fmaf(yv, w1.x, acc[r][4]);
            acc[r][5] = fmaf(yv, w1.y, acc[r][5]);
            acc[r][6] = fmaf(yv, w1.z, acc[r][6]);
            acc[r][7] = fmaf(yv, w1.w, acc[r][7]);
        }
    }
    #pragma unroll
    for (int c = 0; c < 8; c++) {
        float bb = __ldg(&b1[c0 + c]);
        #pragma unroll
        for (int r = 0; r < 4; r++)
            hid[(r0 + r) * HID_STRIDE + c0 + c] = fmaxf(acc[r][c] + bb, 0.f);
    }
    __syncthreads();

    // GEMM2, split-k by 4: group g2 covers k in [g2*64, g2*64+64).
    // W2 read directly from global (40KB, L1-resident).
    int g2 = tid >> 6;       // 0..3
    int u  = tid & 63;
    int cg = u & 7;          // 5 cols: cg*5..+4
    int rg = u >> 3;         // rows rg*4..+3
    float a2[4][5];
    #pragma unroll
    for (int r = 0; r < 4; r++)
        #pragma unroll
        for (int j = 0; j < 5; j++) a2[r][j] = 0.f;

    #pragma unroll 4
    for (int kk = 0; kk < 64; kk++) {
        int k = g2 * 64 + kk;
        float wv[5];
        #pragma unroll
        for (int j = 0; j < 5; j++) wv[j] = __ldg(&W2[k * 40 + cg * 5 + j]);
        #pragma unroll
        for (int r = 0; r < 4; r++) {
            float hv = hid[(rg * 4 + r) * HID_STRIDE + k];
            #pragma unroll
            for (int j = 0; j < 5; j++) a2[r][j] = fmaf(hv, wv[j], a2[r][j]);
        }
    }
    #pragma unroll
    for (int r = 0; r < 4; r++)
        #pragma unroll
        for (int j = 0; j < 5; j++)
            red[g2 * 1280 + (rg * 4 + r) * 40 + cg * 5 + j] = a2[r][j];
    __syncthreads();

    for (int i = tid; i < 1280; i += 256) {
        int r = i / 40, c = i % 40;
        float s = red[i] + red[1280 + i] + red[2560 + i] + red[3840 + i]
                + __ldg(&b2[c]);
        int g = row0 + r;
        if (g < n) out[g * 40 + c] = s;
    }
}

// ---------------- launch ----------------
extern "C" void kernel_launch(void* const* d_in, const int* in_sizes, int n_in,
                              void* d_out, int out_size) {
    const float* x  = (const float*)d_in[0];
    const void*  ei = d_in[1];
    const float* W1 = (const float*)d_in[2];
    const float* b1 = (const float*)d_in[3];
    const float* W2 = (const float*)d_in[4];
    const float* b2 = (const float*)d_in[5];
    float* out = (float*)d_out;

    int n = in_sizes[0] / NFEAT;   // 100000
    int E = in_sizes[1] / 2;       // 1200000

    void *wsp, *h0p, *h1p, *yp, *colp, *wp_;
    cudaGetSymbolAddress(&wsp,  g_ws);
    cudaGetSymbolAddress(&h0p,  g_h0);
    cudaGetSymbolAddress(&h1p,  g_h1);
    cudaGetSymbolAddress(&yp,   g_y);
    cudaGetSymbolAddress(&colp, g_col);
    cudaGetSymbolAddress(&wp_,  g_w);

    cudaMemsetAsync(wsp,  0, (2 * N_NODES_MAX + 256) * sizeof(int), 0);
    cudaMemsetAsync(colp, 0, EP_MAX * sizeof(int), 0);    // pad offsets -> h[0]
    cudaMemsetAsync(wp_,  0, EP_MAX * sizeof(float), 0);  // pad weights -> 0

    int E4 = (E + 3) / 4;
    k_hist<<<(E4 + 255) / 256, 256>>>(ei, E);
    int ntiles = (n + 1023) / 1024;   // 98 (< 148 SMs -> StreamScan safe)
    k_scan<<<ntiles, 1024>>>(n, ntiles);

    int n4 = n * NFEAT / 4;
    int Eb = (E4 + 255) / 256;
    int Nb = (n4 + 255) / 256;
    k_scatter_init<<<Eb + Nb, 256>>>(ei, E, (const float4*)x, n4, Eb);

    float* hA = (float*)h0p;
    float* hB = (float*)h1p;
    int n2 = 2 * n;                               // feature-half warps
    int spmmBlocks = (n2 * 32 + 255) / 256;
    for (int it = 0; it < ORDER; it++) {
        k_spmm<<<spmmBlocks, 256>>>(hA, hB, n2);
        float* t = hA; hA = hB; hB = t;
    }

    size_t smemBytes = (size_t)SMEM_FLOATS * sizeof(float);  // ~61.6 KB
    cudaFuncSetAttribute(k_mlp, cudaFuncAttributeMaxDynamicSharedMemorySize,
                         (int)smemBytes);
    k_mlp<<<(n + 31) / 32, 256, smemBytes>>>((const float*)yp, W1, b1, W2, b2,
                                             out, n);
}

// round 17
// speedup vs baseline: 1.2151x; 1.2151x over previous
#include <cuda_runtime.h>
#include <stdint.h>

#define N_NODES_MAX 100000
#define E_MAX       1200000
#define EP_MAX      (E_MAX + 4 * N_NODES_MAX)   // CSR padded to multiple-of-4 rows
#define NFEAT 64
#define NHID  256
#define NCLASS 40
#define ORDER 8

// ---------------- scratch (device globals; no allocation) ----------------
__device__ __align__(256) float g_h0[N_NODES_MAX * NFEAT];
__device__ __align__(256) float g_h1[N_NODES_MAX * NFEAT];
__device__ __align__(256) float g_y [N_NODES_MAX * NFEAT];
// combined zero-initialized workspace: [0,N)=cnt, [N,2N)=fill, [2N,2N+256)=scan flags
__device__ int   g_ws[2 * N_NODES_MAX + 256];
__device__ float g_dinv[N_NODES_MAX];
__device__ int   g_rowptr[N_NODES_MAX + 1];
__device__ __align__(16) int   g_col[EP_MAX];  // PRE-SCALED byte offsets (col*256); pads = 0
__device__ __align__(16) float g_w  [EP_MAX];  // pad slots = 0.0f (exact no-op in fmaf)

#define CNT(i)  g_ws[i]
#define FILL(i) g_ws[N_NODES_MAX + (i)]
#define FLAG(b) g_ws[2 * N_NODES_MAX + (b)]

// ---------------- edge-index dtype self-detection ----------------
// Reference asks int64 but JAX without x64 silently yields int32. Node ids
// < 1e5, so int32 data reinterpreted as int64 gives values >= 2^32 unless a
// paired high id is exactly 0 (1e-5 per sample; 8 samples -> (1e-5)^8).
__device__ __forceinline__ int detect_is64(const void* ei) {
    const unsigned long long* p = (const unsigned long long*)ei;
    int is64 = 1;
    #pragma unroll
    for (int i = 0; i < 8; i++)
        if (p[i] >= (unsigned long long)N_NODES_MAX) is64 = 0;
    return is64;
}

__device__ __forceinline__ int edge_at(const void* ei, int is64, int idx) {
    if (is64) return (int)((const long long*)ei)[idx];
    return ((const int*)ei)[idx];
}

// Vectorized: load 4 consecutive edge ids starting at idx (idx 4-aligned).
__device__ __forceinline__ void edge_at4(const void* ei, int is64, int idx,
                                         int out[4]) {
    if (is64) {
        const longlong2* p = (const longlong2*)((const long long*)ei + idx);
        longlong2 a = __ldg(&p[0]);
        longlong2 b = __ldg(&p[1]);
        out[0] = (int)a.x; out[1] = (int)a.y;
        out[2] = (int)b.x; out[3] = (int)b.y;
    } else {
        int4 a = __ldg((const int4*)((const int*)ei + idx));
        out[0] = a.x; out[1] = a.y; out[2] = a.z; out[3] = a.w;
    }
}

// ---------------- preprocessing ----------------
// 4 edges per thread, vectorized loads -> 4 atomics in flight per thread.
__global__ void k_hist(const void* __restrict__ ei, int E) {
    int e0 = (blockIdx.x * blockDim.x + threadIdx.x) * 4;
    if (e0 >= E) return;
    int is64 = detect_is64(ei);
    if (e0 + 4 <= E) {
        int r[4];
        edge_at4(ei, is64, e0, r);
        #pragma unroll
        for (int t = 0; t < 4; t++) atomicAdd(&CNT(r[t]), 1);
    } else {
        for (int e = e0; e < E; e++)
            atomicAdd(&CNT(edge_at(ei, is64, e)), 1);
    }
}

// Fused: dinv + exclusive scan of PADDED degree counts -> rowptr.
// Padded degree = (deg+3)&~3 -> branch-free 4-wide groups AND 16B-aligned
// col/w groups. StreamScan: 98 resident blocks, serial FLAG chain,
// distinct poll addresses -> no contention.
__global__ __launch_bounds__(1024) void k_scan(int n, int ntiles) {
    __shared__ int s[1024];
    __shared__ int s_prefix;
    int tid = threadIdx.x;
    int b   = blockIdx.x;
    int i   = b * 1024 + tid;
    int c   = (i < n) ? CNT(i) : 0;
    int cp  = (c + 3) & ~3;                          // padded degree
    if (i < n) g_dinv[i] = rsqrtf((float)(c + 1));   // +1 self-loop (actual deg)
    s[tid] = cp;
    __syncthreads();
    #pragma unroll
    for (int off = 1; off < 1024; off <<= 1) {
        int t = (tid >= off) ? s[tid - off] : 0;
        __syncthreads();
        s[tid] += t;
        __syncthreads();
    }
    if (tid == 1023) {
        int prefix = 0;
        if (b > 0) {
            int v;
            do { v = atomicAdd(&FLAG(b - 1), 0); } while (v == 0);
            prefix = v - 1;
        }
        atomicExch(&FLAG(b), prefix + s[1023] + 1);
        s_prefix = prefix;
        if (b == ntiles - 1) g_rowptr[n] = prefix + s[1023];  // total padded
    }
    __syncthreads();
    if (i < n) g_rowptr[i] = s_prefix + s[tid] - cp;  // exclusive
}

// Fused: CSR scatter (blocks [0,Eb)) + h0/y init (blocks [Eb, Eb+Nb)).
__global__ void k_scatter_init(const void* __restrict__ ei, int E,
                               const float4* __restrict__ x, int n4, int Eb) {
    if ((int)blockIdx.x < Eb) {
        int e0 = (blockIdx.x * blockDim.x + threadIdx.x) * 4;
        if (e0 >= E) return;
        int is64 = detect_is64(ei);
        if (e0 + 4 <= E) {
            int r[4], c[4];
            edge_at4(ei, is64, e0, r);
            edge_at4(ei, is64, E + e0, c);
            #pragma unroll
            for (int t = 0; t < 4; t++) {
                int pos = g_rowptr[r[t]] + atomicAdd(&FILL(r[t]), 1);
                g_col[pos] = c[t] * (NFEAT * 4);
                g_w[pos] = g_dinv[r[t]] * g_dinv[c[t]];
            }
        } else {
            for (int e = e0; e < E; e++) {
                int r = edge_at(ei, is64, e);
                int c = edge_at(ei, is64, E + e);
                int pos = g_rowptr[r] + atomicAdd(&FILL(r), 1);
                g_col[pos] = c * (NFEAT * 4);
                g_w[pos] = g_dinv[r] * g_dinv[c];
            }
        }
    } else {
        int i = ((int)blockIdx.x - Eb) * blockDim.x + threadIdx.x;
        if (i < n4) {
            float4 v = x[i];
            v.x *= 0.5f; v.y *= 0.5f; v.z *= 0.5f; v.w *= 0.5f;
            ((float4*)g_h0)[i] = v;
            ((float4*)g_y)[i]  = v;
        }
    }
}

// ---------------- SPMM: warp-per-FULL-row, 8 gathers in flight -------------
// Synthesis of R5+R11 measurements: ONE warp per row (one metadata walk,
// one overhead block — R11's half-row split regressed 1.5x), float2 per
// lane. Kept from R11: padded branch-free groups, int4+float4 metadata
// loads, byte-offset addressing. New: 8 edges per iteration (2 groups, the
// 2nd predicated by ONE test per 8 edges) -> 8 independent gathers in
// flight to cover ~250cyc L2 latency. hdst uses NORMAL stores (it is next
// hop's gather source); only y (touched once/hop) uses streaming.
__global__ __launch_bounds__(256, 4) void k_spmm(const float* __restrict__ hsrc,
                                                 float* __restrict__ hdst,
                                                 int n) {
    int w = (blockIdx.x * blockDim.x + threadIdx.x) >> 5;
    if (w >= n) return;
    int lane = threadIdx.x & 31;
    int l8 = lane * 8;                       // byte offset of this lane's float2
    const char* __restrict__ hb = (const char*)hsrc;
    float dv = g_dinv[w];
    float2 hv = ((const float2*)hsrc)[w * 32 + lane];
    float sw = dv * dv;                      // self-loop weight
    float2 a0, a1, a2, a3;
    a0.x = sw * hv.x; a0.y = sw * hv.y;
    a1.x = 0.f; a1.y = 0.f; a2.x = 0.f; a2.y = 0.f; a3.x = 0.f; a3.y = 0.f;
    int beg = g_rowptr[w], end = g_rowptr[w + 1];  // multiples of 4
    for (int j = beg; j < end; j += 8) {
        int4   o0 = __ldg((const int4*)&g_col[j]);
        float4 w0 = __ldg((const float4*)&g_w[j]);
        bool p = (j + 4 < end);
        int jb = p ? j + 4 : j;                       // clamped: always valid
        int4   o1 = __ldg((const int4*)&g_col[jb]);
        float4 w1 = __ldg((const float4*)&g_w[jb]);
        if (!p) { w1.x = 0.f; w1.y = 0.f; w1.z = 0.f; w1.w = 0.f; }
        float2 v0 = *(const float2*)(hb + o0.x + l8);
        float2 v1 = *(const float2*)(hb + o0.y + l8);
        float2 v2 = *(const float2*)(hb + o0.z + l8);
        float2 v3 = *(const float2*)(hb + o0.w + l8);
        float2 v4 = *(const float2*)(hb + o1.x + l8);
        float2 v5 = *(const float2*)(hb + o1.y + l8);
        float2 v6 = *(const float2*)(hb + o1.z + l8);
        float2 v7 = *(const float2*)(hb + o1.w + l8);
        a0.x = fmaf(w0.x, v0.x, a0.x);  a0.y = fmaf(w0.x, v0.y, a0.y);
        a1.x = fmaf(w0.y, v1.x, a1.x);  a1.y = fmaf(w0.y, v1.y, a1.y);
        a2.x = fmaf(w0.z, v2.x, a2.x);  a2.y = fmaf(w0.z, v2.y, a2.y);
        a3.x = fmaf(w0.w, v3.x, a3.x);  a3.y = fmaf(w0.w, v3.y, a3.y);
        a0.x = fmaf(w1.x, v4.x, a0.x);  a0.y = fmaf(w1.x, v4.y, a0.y);
        a1.x = fmaf(w1.y, v5.x, a1.x);  a1.y = fmaf(w1.y, v5.y, a1.y);
        a2.x = fmaf(w1.z, v6.x, a2.x);  a2.y = fmaf(w1.z, v6.y, a2.y);
        a3.x = fmaf(w1.w, v7.x, a3.x);  a3.y = fmaf(w1.w, v7.y, a3.y);
    }
    float2 a;
    a.x = (a0.x + a1.x) + (a2.x + a3.x);
    a.y = (a0.y + a1.y) + (a2.y + a3.y);
    int idx = w * 32 + lane;
    ((float2*)hdst)[idx] = a;                    // NORMAL store: next hop reads it
    float2* yp = (float2*)g_y;
    float2 yy = __ldcs(&yp[idx]);                // y touched once/hop: streaming
    yy.x += a.x; yy.y += a.y;
    __stcs(&yp[idx], yy);
}

// ---------------- fused MLP: relu(y/9 @ W1 + b1) @ W2 + b2 ----------------
// UNCHANGED from R11 — measured WIN (~290us -> ~110us by ledger): weights
// read from L1-resident global (no smem staging); smem 61.6KB -> 3 blocks/SM.
#define HID_STRIDE 257
#define SMEM_FLOATS (32*64 + 32*HID_STRIDE + 4*32*40)

__global__ __launch_bounds__(256) void k_mlp(const float* __restrict__ y,
                                             const float* __restrict__ W1,
                                             const float* __restrict__ b1,
                                             const float* __restrict__ W2,
                                             const float* __restrict__ b2,
                                             float* __restrict__ out, int n) {
    extern __shared__ float sm[];
    float* ys  = sm;                    // [32][64]
    float* hid = ys + 32 * 64;          // [32][HID_STRIDE]
    float* red = hid + 32 * HID_STRIDE; // [4][32][40] split-k partials

    int tid = threadIdx.x;
    int row0 = blockIdx.x * 32;
    const float inv9 = 1.0f / 9.0f;

    for (int i = tid; i < 32 * 64; i += 256) {
        int r = i >> 6, g = row0 + r;
        ys[i] = (g < n) ? y[g * 64 + (i & 63)] * inv9 : 0.f;
    }
    __syncthreads();

    int lane = tid & 31, warp = tid >> 5;
    int r0 = warp * 4;
    int c0 = lane * 8;
    float acc[4][8];
    #pragma unroll
    for (int r = 0; r < 4; r++)
        #pragma unroll
        for (int c = 0; c < 8; c++) acc[r][c] = 0.f;

    #pragma unroll 4
    for (int k = 0; k < 64; k++) {
        float4 w0 = __ldg((const float4*)&W1[k * 256 + c0]);
        float4 w1 = __ldg((const float4*)&W1[k * 256 + c0 + 4]);
        #pragma unroll
        for (int r = 0; r < 4; r++) {
            float yv = ys[(r0 + r) * 64 + k];
            acc[r][0] = fmaf(yv, w0.x, acc[r][0]);
            acc[r][1] = fmaf(yv, w0.y, acc[r][1]);
            acc[r][2] = fmaf(yv, w0.z, acc[r][2]);
            acc[r][3] = fmaf(yv, w0.w, acc[r][3]);
            acc[r][4] = fmaf(yv, w1.x, acc[r][4]);
            acc[r][5] = fmaf(yv, w1.y, acc[r][5]);
            acc[r][6] = fmaf(yv, w1.z, acc[r][6]);
            acc[r][7] = fmaf(yv, w1.w, acc[r][7]);
        }
    }
    #pragma unroll
    for (int c = 0; c < 8; c++) {
        float bb = __ldg(&b1[c0 + c]);
        #pragma unroll
        for (int r = 0; r < 4; r++)
            hid[(r0 + r) * HID_STRIDE + c0 + c] = fmaxf(acc[r][c] + bb, 0.f);
    }
    __syncthreads();

    int g2 = tid >> 6;
    int u  = tid & 63;
    int cg = u & 7;
    int rg = u >> 3;
    float a2[4][5];
    #pragma unroll
    for (int r = 0; r < 4; r++)
        #pragma unroll
        for (int j = 0; j < 5; j++) a2[r][j] = 0.f;

    #pragma unroll 4
    for (int kk = 0; kk < 64; kk++) {
        int k = g2 * 64 + kk;
        float wv[5];
        #pragma unroll
        for (int j = 0; j < 5; j++) wv[j] = __ldg(&W2[k * 40 + cg * 5 + j]);
        #pragma unroll
        for (int r = 0; r < 4; r++) {
            float hv = hid[(rg * 4 + r) * HID_STRIDE + k];
            #pragma unroll
            for (int j = 0; j < 5; j++) a2[r][j] = fmaf(hv, wv[j], a2[r][j]);
        }
    }
    #pragma unroll
    for (int r = 0; r < 4; r++)
        #pragma unroll
        for (int j = 0; j < 5; j++)
            red[g2 * 1280 + (rg * 4 + r) * 40 + cg * 5 + j] = a2[r][j];
    __syncthreads();

    for (int i = tid; i < 1280; i += 256) {
        int r = i / 40, c = i % 40;
        float s = red[i] + red[1280 + i] + red[2560 + i] + red[3840 + i]
                + __ldg(&b2[c]);
        int g = row0 + r;
        if (g < n) out[g * 40 + c] = s;
    }
}

// ---------------- launch ----------------
extern "C" void kernel_launch(void* const* d_in, const int* in_sizes, int n_in,
                              void* d_out, int out_size) {
    const float* x  = (const float*)d_in[0];
    const void*  ei = d_in[1];
    const float* W1 = (const float*)d_in[2];
    const float* b1 = (const float*)d_in[3];
    const float* W2 = (const float*)d_in[4];
    const float* b2 = (const float*)d_in[5];
    float* out = (float*)d_out;

    int n = in_sizes[0] / NFEAT;   // 100000
    int E = in_sizes[1] / 2;       // 1200000

    void *wsp, *h0p, *h1p, *yp, *colp, *wp_;
    cudaGetSymbolAddress(&wsp,  g_ws);
    cudaGetSymbolAddress(&h0p,  g_h0);
    cudaGetSymbolAddress(&h1p,  g_h1);
    cudaGetSymbolAddress(&yp,   g_y);
    cudaGetSymbolAddress(&colp, g_col);
    cudaGetSymbolAddress(&wp_,  g_w);

    cudaMemsetAsync(wsp,  0, (2 * N_NODES_MAX + 256) * sizeof(int), 0);
    cudaMemsetAsync(colp, 0, EP_MAX * sizeof(int), 0);    // pad offsets -> h[0]
    cudaMemsetAsync(wp_,  0, EP_MAX * sizeof(float), 0);  // pad weights -> 0

    int E4 = (E + 3) / 4;
    k_hist<<<(E4 + 255) / 256, 256>>>(ei, E);
    int ntiles = (n + 1023) / 1024;   // 98 (< 148 SMs -> StreamScan safe)
    k_scan<<<ntiles, 1024>>>(n, ntiles);

    int n4 = n * NFEAT / 4;
    int Eb = (E4 + 255) / 256;
    int Nb = (n4 + 255) / 256;
    k_scatter_init<<<Eb + Nb, 256>>>(ei, E, (const float4*)x, n4, Eb);

    float* hA = (float*)h0p;
    float* hB = (float*)h1p;
    int spmmBlocks = (n * 32 + 255) / 256;        // warp per FULL row
    for (int it = 0; it < ORDER; it++) {
        k_spmm<<<spmmBlocks, 256>>>(hA, hB, n);
        float* t = hA; hA = hB; hB = t;
    }

    size_t smemBytes = (size_t)SMEM_FLOATS * sizeof(float);  // ~61.6 KB
    cudaFuncSetAttribute(k_mlp, cudaFuncAttributeMaxDynamicSharedMemorySize,
                         (int)smemBytes);
    k_mlp<<<(n + 31) / 32, 256, smemBytes>>>((const float*)yp, W1, b1, W2, b2,
                                             out, n);
}